// round 4
// baseline (speedup 1.0000x reference)
#include <cuda_runtime.h>

// Causal attention: S=2048, B=1, H=24, D=128, fp32 in/out, TF32 tensor cores.
// Inputs [S,B,H,D] (B=1 -> contiguous [S,H,D]); output [B,S,H*D] same layout.
#define S_LEN 2048
#define H_NUM 24
#define D_DIM 128
#define ROWSTRIDE (H_NUM * D_DIM)
#define BM 128                       // q rows per CTA (16 per warp, 8 warps)
#define BN 64                        // k tokens per iteration
#define QS 132                       // sQ/sK row stride (==4 mod 32 -> LDSM conflict-free)
#define PS 68                        // sP row stride (==4 mod 32)
#define VG 132                       // V frag group stride (128 payload + 4 pad)
#define NTH 256

__device__ __forceinline__ unsigned f2tf(float x) {
    unsigned r;
    asm("cvt.rna.tf32.f32 %0, %1;" : "=r"(r) : "f"(x));
    return r;
}

__device__ __forceinline__ void ldsm4(unsigned& r0, unsigned& r1,
                                      unsigned& r2, unsigned& r3, unsigned a) {
    asm volatile("ldmatrix.sync.aligned.m8n8.x4.shared.b16 {%0,%1,%2,%3},[%4];"
                 : "=r"(r0), "=r"(r1), "=r"(r2), "=r"(r3) : "r"(a));
}

__device__ __forceinline__ void mma8(float c[4], unsigned a0, unsigned a1,
                                     unsigned a2, unsigned a3,
                                     unsigned b0, unsigned b1) {
    asm volatile(
        "mma.sync.aligned.m16n8k8.row.col.f32.tf32.tf32.f32 "
        "{%0,%1,%2,%3},{%4,%5,%6,%7},{%8,%9},{%0,%1,%2,%3};"
        : "+f"(c[0]), "+f"(c[1]), "+f"(c[2]), "+f"(c[3])
        : "r"(a0), "r"(a1), "r"(a2), "r"(a3), "r"(b0), "r"(b1));
}

__global__ __launch_bounds__(NTH, 1)
void attn_fwd(const float* __restrict__ Qg, const float* __restrict__ Kg,
              const float* __restrict__ Vg, float* __restrict__ Og) {
    extern __shared__ float smem[];
    float* sQ  = smem;                    // [BM][QS]
    float* sK  = sQ + BM * QS;            // [BN][QS]
    float* sVf = sK + BN * QS;            // [64 groups][VG] fragment-major V
    float* sP  = sVf + 64 * VG;           // [BM][PS]

    const int qb = gridDim.x - 1 - blockIdx.x;   // heavy blocks first
    const int h  = blockIdx.y;
    const int q0 = qb * BM;
    const int tid  = threadIdx.x;
    const int lane = tid & 31;
    const int w    = tid >> 5;
    const int la   = lane & 3;
    const int lb   = lane >> 2;

    const float scale = 0.08838834764831845f;  // 1/sqrt(128)

    // ---- Load Q tile [BM x 128], pre-scaled, tf32-rounded ----
    {
        const float* qbase = Qg + (size_t)q0 * ROWSTRIDE + h * D_DIM;
        #pragma unroll
        for (int it = 0; it < (BM * 32) / NTH; ++it) {
            int idx = tid + it * NTH;
            int r = idx >> 5, c4 = idx & 31;
            float4 v = *(const float4*)(qbase + (size_t)r * ROWSTRIDE + c4 * 4);
            v.x = __uint_as_float(f2tf(v.x * scale));
            v.y = __uint_as_float(f2tf(v.y * scale));
            v.z = __uint_as_float(f2tf(v.z * scale));
            v.w = __uint_as_float(f2tf(v.w * scale));
            *(float4*)(sQ + r * QS + c4 * 4) = v;
        }
    }

    float o[16][4];
    #pragma unroll
    for (int t = 0; t < 16; ++t)
        #pragma unroll
        for (int j = 0; j < 4; ++j) o[t][j] = 0.f;
    float m0 = -1e30f, m1 = -1e30f, l0 = 0.f, l1 = 0.f;

    float* sPw = sP + w * 16 * PS;

    // LDSM base addresses (byte units). Tile select: lanes 0-7 tile0, 8-15 tile1
    // (cols +4), 16-23 tile2 (rows +8), 24-31 tile3 (rows +8, cols +4).
    const int trow = (lane & 7) + ((lane >> 4) & 1) * 8;   // row within 16-row tile
    const int tcol = ((lane >> 3) & 1) * 4;                // b32 col offset 0/4
    const unsigned qA_base = (unsigned)__cvta_generic_to_shared(
        sQ + (w * 16 + trow) * QS + tcol);
    const unsigned kB_base = (unsigned)__cvta_generic_to_shared(
        sK + trow * QS + tcol);   // + np*16*QS rows, + kk*8 cols
    const unsigned pA_base = (unsigned)__cvta_generic_to_shared(
        sPw + trow * PS + tcol);

    const int nkb = 2 * qb + 2;
    for (int kb = 0; kb < nkb; ++kb) {
        __syncthreads();

        // ---- Load K (natural layout) and V (fragment-major) ----
        {
            const int k0g = kb * BN;
            const float* kbase = Kg + (size_t)k0g * ROWSTRIDE + h * D_DIM;
            const float* vbase = Vg + (size_t)k0g * ROWSTRIDE + h * D_DIM;
            #pragma unroll
            for (int it = 0; it < (BN * 32) / NTH; ++it) {
                int idx = tid + it * NTH;
                int r = idx >> 5, c4 = idx & 31;
                float4 kv = *(const float4*)(kbase + (size_t)r * ROWSTRIDE + c4 * 4);
                float4 vv = *(const float4*)(vbase + (size_t)r * ROWSTRIDE + c4 * 4);
                kv.x = __uint_as_float(f2tf(kv.x));
                kv.y = __uint_as_float(f2tf(kv.y));
                kv.z = __uint_as_float(f2tf(kv.z));
                kv.w = __uint_as_float(f2tf(kv.w));
                *(float4*)(sK + r * QS + c4 * 4) = kv;

                // V frag store: element (token r, col c) ->
                // group (kk*8 + t2)*VG + (lb*4+la)*4 + teven*2 + pair
                const int kk   = r >> 3;
                const int vla  = r & 3;
                const int pair = (r >> 2) & 1;
                const int t2    = c4 >> 2;
                const int tev   = (c4 >> 1) & 1;
                float* g = sVf + (kk * 8 + t2) * VG + tev * 2 + pair + vla * 4;
                g[((c4 & 1) * 4 + 0) * 16] = __uint_as_float(f2tf(vv.x));
                g[((c4 & 1) * 4 + 1) * 16] = __uint_as_float(f2tf(vv.y));
                g[((c4 & 1) * 4 + 2) * 16] = __uint_as_float(f2tf(vv.z));
                g[((c4 & 1) * 4 + 3) * 16] = __uint_as_float(f2tf(vv.w));
            }
        }
        __syncthreads();

        // ---- S = Q K^T : warp computes [16 x 64] via ldmatrix + mma ----
        float sc[8][4];
        #pragma unroll
        for (int n = 0; n < 8; ++n)
            #pragma unroll
            for (int j = 0; j < 4; ++j) sc[n][j] = 0.f;

        #pragma unroll
        for (int kk = 0; kk < 16; ++kk) {
            unsigned a0, a1, a2, a3;
            ldsm4(a0, a2, a1, a3, qA_base + kk * 32);   // r1=cols+4 -> a2, r2=rows+8 -> a1
            #pragma unroll
            for (int np = 0; np < 4; ++np) {
                unsigned b0, b1, b2, b3;
                ldsm4(b0, b1, b2, b3, kB_base + (np * 16 * QS) * 4 + kk * 32);
                mma8(sc[2 * np],     a0, a1, a2, a3, b0, b1);
                mma8(sc[2 * np + 1], a0, a1, a2, a3, b2, b3);
            }
        }

        // ---- causal mask ----
        const int row_lo = q0 + w * 16 + lb;
        if (kb * BN >= q0) {
            #pragma unroll
            for (int n = 0; n < 8; ++n) {
                const int col = kb * BN + n * 8 + 2 * la;
                if (col     > row_lo)     sc[n][0] = -1e30f;
                if (col + 1 > row_lo)     sc[n][1] = -1e30f;
                if (col     > row_lo + 8) sc[n][2] = -1e30f;
                if (col + 1 > row_lo + 8) sc[n][3] = -1e30f;
            }
        }

        // ---- online softmax ----
        float mx0 = -1e30f, mx1 = -1e30f;
        #pragma unroll
        for (int n = 0; n < 8; ++n) {
            mx0 = fmaxf(mx0, fmaxf(sc[n][0], sc[n][1]));
            mx1 = fmaxf(mx1, fmaxf(sc[n][2], sc[n][3]));
        }
        mx0 = fmaxf(mx0, __shfl_xor_sync(0xffffffffu, mx0, 1));
        mx0 = fmaxf(mx0, __shfl_xor_sync(0xffffffffu, mx0, 2));
        mx1 = fmaxf(mx1, __shfl_xor_sync(0xffffffffu, mx1, 1));
        mx1 = fmaxf(mx1, __shfl_xor_sync(0xffffffffu, mx1, 2));

        const float mn0 = fmaxf(m0, mx0);
        const float mn1 = fmaxf(m1, mx1);
        const float corr0 = __expf(m0 - mn0);
        const float corr1 = __expf(m1 - mn1);
        m0 = mn0; m1 = mn1;

        float rs0 = 0.f, rs1 = 0.f;
        #pragma unroll
        for (int n = 0; n < 8; ++n) {
            float p0 = __expf(sc[n][0] - mn0);
            float p1 = __expf(sc[n][1] - mn0);
            float p2 = __expf(sc[n][2] - mn1);
            float p3 = __expf(sc[n][3] - mn1);
            rs0 += p0 + p1;
            rs1 += p2 + p3;
            *(float2*)(sPw + lb * PS + n * 8 + 2 * la) =
                make_float2(__uint_as_float(f2tf(p0)), __uint_as_float(f2tf(p1)));
            *(float2*)(sPw + (lb + 8) * PS + n * 8 + 2 * la) =
                make_float2(__uint_as_float(f2tf(p2)), __uint_as_float(f2tf(p3)));
        }
        rs0 += __shfl_xor_sync(0xffffffffu, rs0, 1);
        rs0 += __shfl_xor_sync(0xffffffffu, rs0, 2);
        rs1 += __shfl_xor_sync(0xffffffffu, rs1, 1);
        rs1 += __shfl_xor_sync(0xffffffffu, rs1, 2);
        l0 = l0 * corr0 + rs0;
        l1 = l1 * corr1 + rs1;

        #pragma unroll
        for (int t = 0; t < 16; ++t) {
            o[t][0] *= corr0; o[t][1] *= corr0;
            o[t][2] *= corr1; o[t][3] *= corr1;
        }
        __syncwarp();   // sP visible within warp

        // ---- O += P V : ldmatrix A (P) + vector-LDS B (V frags) ----
        #pragma unroll
        for (int kk = 0; kk < 8; ++kk) {
            unsigned a0, a1, a2, a3;
            ldsm4(a0, a2, a1, a3, pA_base + kk * 32);
            const float* vb = sVf + kk * 8 * VG + lane * 4;
            #pragma unroll
            for (int t2 = 0; t2 < 8; ++t2) {
                float4 vv = *(const float4*)(vb + t2 * VG);
                mma8(o[2 * t2],     a0, a1, a2, a3,
                     __float_as_uint(vv.x), __float_as_uint(vv.y));
                mma8(o[2 * t2 + 1], a0, a1, a2, a3,
                     __float_as_uint(vv.z), __float_as_uint(vv.w));
            }
        }
        __syncwarp();   // P reads done before next overwrite
    }

    // ---- epilogue: normalize, store ----
    const float inv0 = 1.f / l0;
    const float inv1 = 1.f / l1;
    const int row0 = q0 + w * 16 + lb;
    const int row1 = row0 + 8;
    float* o0 = Og + (size_t)row0 * ROWSTRIDE + h * D_DIM;
    float* o1 = Og + (size_t)row1 * ROWSTRIDE + h * D_DIM;
    #pragma unroll
    for (int t = 0; t < 16; ++t) {
        *(float2*)(o0 + t * 8 + 2 * la) = make_float2(o[t][0] * inv0, o[t][1] * inv0);
        *(float2*)(o1 + t * 8 + 2 * la) = make_float2(o[t][2] * inv1, o[t][3] * inv1);
    }
}

extern "C" void kernel_launch(void* const* d_in, const int* in_sizes, int n_in,
                              void* d_out, int out_size) {
    const float* Q = (const float*)d_in[0];
    const float* K = (const float*)d_in[1];
    const float* V = (const float*)d_in[2];
    float* O = (float*)d_out;

    const size_t smem_bytes =
        (size_t)(BM * QS + BN * QS + 64 * VG + BM * PS) * sizeof(float);  // 169984 B

    cudaFuncSetAttribute(attn_fwd, cudaFuncAttributeMaxDynamicSharedMemorySize,
                         (int)smem_bytes);

    dim3 grid(S_LEN / BM, H_NUM);
    attn_fwd<<<grid, NTH, smem_bytes>>>(Q, K, V, O);
}